// round 3
// baseline (speedup 1.0000x reference)
#include <cuda_runtime.h>
#include <math.h>

// Problem constants
static constexpr int kB = 8;
static constexpr int kN = 2048;
static constexpr int kU = 256;   // UNITS
static constexpr int kH = 8;     // heads
static constexpr int kD = 32;    // head dim
static constexpr int kM = kB * kN;  // 16384 rows

// Scratch (allocation-free rule: __device__ globals). 16 MB each.
__device__ __align__(256) float g_q[(size_t)kB * kH * kN * kD];
__device__ __align__(256) float g_k[(size_t)kB * kH * kN * kD];
__device__ __align__(256) float g_v[(size_t)kB * kH * kN * kD];
__device__ __align__(256) float g_ctx[(size_t)kB * kH * kN * kD];

// ---------------------------------------------------------------------------
// Kernel 1: fused QKV projection.
// OUT[m, c] = X[m, :] @ W[:, c] for W in {Wq, Wk, Wv} (c tiled over 768).
// Writes into g_q/g_k/g_v with [B, H, N, D] layout for the attention kernel.
// CTA: 64x64 output tile, 256 threads, 4x4 accum per thread.
// ---------------------------------------------------------------------------
__global__ __launch_bounds__(256) void proj_qkv_kernel(
    const float* __restrict__ X,
    const float* __restrict__ Wq,
    const float* __restrict__ Wk,
    const float* __restrict__ Wv)
{
    __shared__ float Xs[64][65];   // [row][k], +1 pad
    __shared__ float Ws[64 * 64];  // [k][col]

    const int t  = threadIdx.x;
    const int tx = t & 15;         // col group (4 cols)
    const int ty = t >> 4;         // row group (4 rows)
    const int m0  = blockIdx.x * 64;
    const int ci0 = blockIdx.y * 64;         // 0..767
    const int mat = ci0 >> 8;                // 0=Q,1=K,2=V
    const int c0  = ci0 & 255;               // col base within the matrix
    const float* __restrict__ W = (mat == 0) ? Wq : (mat == 1) ? Wk : Wv;

    float acc[4][4];
    #pragma unroll
    for (int i = 0; i < 4; i++)
        #pragma unroll
        for (int j = 0; j < 4; j++) acc[i][j] = 0.f;

    for (int k0 = 0; k0 < kU; k0 += 64) {
        __syncthreads();
        #pragma unroll
        for (int r = 0; r < 4; r++) {
            int row = (t >> 4) + 16 * r;     // 0..63
            int kc  = (t & 15) * 4;          // 0..60
            float4 x4 = *(const float4*)&X[(size_t)(m0 + row) * kU + k0 + kc];
            Xs[row][kc + 0] = x4.x; Xs[row][kc + 1] = x4.y;
            Xs[row][kc + 2] = x4.z; Xs[row][kc + 3] = x4.w;
            float4 w4 = *(const float4*)&W[(size_t)(k0 + row) * kU + c0 + kc];
            *(float4*)&Ws[row * 64 + kc] = w4;
        }
        __syncthreads();

        #pragma unroll 8
        for (int k = 0; k < 64; k++) {
            float a0 = Xs[4 * ty + 0][k];
            float a1 = Xs[4 * ty + 1][k];
            float a2 = Xs[4 * ty + 2][k];
            float a3 = Xs[4 * ty + 3][k];
            float4 b4 = *(const float4*)&Ws[k * 64 + 4 * tx];
            acc[0][0] += a0 * b4.x; acc[0][1] += a0 * b4.y; acc[0][2] += a0 * b4.z; acc[0][3] += a0 * b4.w;
            acc[1][0] += a1 * b4.x; acc[1][1] += a1 * b4.y; acc[1][2] += a1 * b4.z; acc[1][3] += a1 * b4.w;
            acc[2][0] += a2 * b4.x; acc[2][1] += a2 * b4.y; acc[2][2] += a2 * b4.z; acc[2][3] += a2 * b4.w;
            acc[3][0] += a3 * b4.x; acc[3][1] += a3 * b4.y; acc[3][2] += a3 * b4.z; acc[3][3] += a3 * b4.w;
        }
    }

    // Epilogue: scatter into [B, H, N, D] layout. 4 consecutive cols stay in one head.
    const int hh = (c0 + 4 * tx) >> 5;
    const int dd = (c0 + 4 * tx) & 31;
    float* __restrict__ dst = (mat == 0) ? g_q : (mat == 1) ? g_k : g_v;
    #pragma unroll
    for (int i = 0; i < 4; i++) {
        int m  = m0 + 4 * ty + i;
        int bb = m >> 11;       // /2048
        int nn = m & 2047;
        *(float4*)&dst[((((size_t)bb * kH + hh) * kN) + nn) * kD + dd] =
            make_float4(acc[i][0], acc[i][1], acc[i][2], acc[i][3]);
    }
}

// ---------------------------------------------------------------------------
// Kernel 2: masked multi-head attention, flash-style online softmax.
// CTA = (batch b, 32-query tile), 8 warps = 8 heads, lane = query.
// All heads share one adjacency tile (read once from DRAM).
// K/V streamed in 16-key tiles through smem; scores/ctx entirely in registers.
// ---------------------------------------------------------------------------
__global__ __launch_bounds__(256, 2) void attn_kernel(const int* __restrict__ adj)
{
    __shared__ float Ks[kH * 16 * kD];  // [h][kj][d]
    __shared__ float Vs[kH * 16 * kD];
    __shared__ int   adjs[16 * 33];     // [kj][qi], +1 pad -> conflict-free

    const int b    = blockIdx.x;
    const int q0   = blockIdx.y * 32;
    const int h    = threadIdx.x >> 5;   // warp = head
    const int lane = threadIdx.x & 31;   // lane = query within tile

    const float scale = 0.17677669529663687f;  // 1/sqrt(32)

    // Q row for this (b, h, q) in registers, pre-scaled.
    float q[32];
    {
        const float4* Qg =
            (const float4*)&g_q[((((size_t)b * kH + h) * kN) + q0 + lane) * kD];
        #pragma unroll
        for (int i = 0; i < 8; i++) {
            float4 v = Qg[i];
            q[4 * i + 0] = v.x * scale; q[4 * i + 1] = v.y * scale;
            q[4 * i + 2] = v.z * scale; q[4 * i + 3] = v.w * scale;
        }
    }

    float ctx[32];
    #pragma unroll
    for (int i = 0; i < 32; i++) ctx[i] = 0.f;
    float mrun = -1e30f;
    float lrun = 0.f;

    const float4* Kg = (const float4*)&g_k[(((size_t)b * kH + h) * kN) * kD];
    const float4* Vg = (const float4*)&g_v[(((size_t)b * kH + h) * kN) * kD];
    float4* Kd = (float4*)&Ks[h * 16 * kD];
    float4* Vd = (float4*)&Vs[h * 16 * kD];

    const int aqi = threadIdx.x >> 3;        // 0..31 query
    const int akj = (threadIdx.x & 7) * 2;   // 0..14 key (pairs)

    for (int kt = 0; kt < kN / 16; kt++) {
        const int k0 = kt * 16;
        __syncthreads();
        // Warp h loads its head's 16x32 K and V tiles (contiguous, coalesced).
        #pragma unroll
        for (int i = 0; i < 4; i++) {
            Kd[lane + 32 * i] = Kg[k0 * 8 + lane + 32 * i];
            Vd[lane + 32 * i] = Vg[k0 * 8 + lane + 32 * i];
        }
        // Adjacency tile [32 q][16 k], stored transposed [kj][qi].
        {
            int2 a2 = *(const int2*)&adj[(((size_t)b * kN) + q0 + aqi) * kN + k0 + akj];
            adjs[(akj + 0) * 33 + aqi] = a2.x;
            adjs[(akj + 1) * 33 + aqi] = a2.y;
        }
        __syncthreads();

        const float4* Kh = (const float4*)&Ks[h * 16 * kD];
        float p[16];
        float tmax = -1e30f;
        #pragma unroll
        for (int kj = 0; kj < 16; kj++) {
            float s0 = 0.f, s1 = 0.f, s2 = 0.f, s3 = 0.f;
            #pragma unroll
            for (int i = 0; i < 8; i++) {
                float4 kv = Kh[kj * 8 + i];  // warp-uniform -> smem broadcast
                s0 += q[4 * i + 0] * kv.x; s1 += q[4 * i + 1] * kv.y;
                s2 += q[4 * i + 2] * kv.z; s3 += q[4 * i + 3] * kv.w;
            }
            float s = (s0 + s1) + (s2 + s3);
            s = (adjs[kj * 33 + lane] > 0) ? s : -1e9f;  // same -1e9 as reference
            p[kj] = s;
            tmax = fmaxf(tmax, s);
        }

        const float mnew  = fmaxf(mrun, tmax);
        const float alpha = __expf(mrun - mnew);
        lrun *= alpha;
        #pragma unroll
        for (int i = 0; i < 32; i++) ctx[i] *= alpha;

        const float4* Vh = (const float4*)&Vs[h * 16 * kD];
        #pragma unroll
        for (int kj = 0; kj < 16; kj++) {
            float pv = __expf(p[kj] - mnew);
            lrun += pv;
            #pragma unroll
            for (int i = 0; i < 8; i++) {
                float4 vv = Vh[kj * 8 + i];
                ctx[4 * i + 0] += pv * vv.x; ctx[4 * i + 1] += pv * vv.y;
                ctx[4 * i + 2] += pv * vv.z; ctx[4 * i + 3] += pv * vv.w;
            }
        }
        mrun = mnew;
    }

    const float inv = 1.f / lrun;
    float4* Cg = (float4*)&g_ctx[((((size_t)b * kH + h) * kN) + q0 + lane) * kD];
    #pragma unroll
    for (int i = 0; i < 8; i++)
        Cg[i] = make_float4(ctx[4 * i + 0] * inv, ctx[4 * i + 1] * inv,
                            ctx[4 * i + 2] * inv, ctx[4 * i + 3] * inv);
}

// ---------------------------------------------------------------------------
// Kernel 3: output projection. OUT = CTX @ Wo + bo.
// CTX is read from the [B, H, N, D] layout (gathered per 32-wide head block).
// ---------------------------------------------------------------------------
__global__ __launch_bounds__(256) void out_proj_kernel(
    const float* __restrict__ Wo,
    const float* __restrict__ bo,
    float* __restrict__ out)
{
    __shared__ float Xs[64][65];
    __shared__ float Ws[64 * 64];

    const int t  = threadIdx.x;
    const int tx = t & 15;
    const int ty = t >> 4;
    const int m0 = blockIdx.x * 64;
    const int c0 = blockIdx.y * 64;

    float acc[4][4];
    #pragma unroll
    for (int i = 0; i < 4; i++)
        #pragma unroll
        for (int j = 0; j < 4; j++) acc[i][j] = 0.f;

    for (int k0 = 0; k0 < kU; k0 += 64) {
        __syncthreads();
        #pragma unroll
        for (int r = 0; r < 4; r++) {
            int row = (t >> 4) + 16 * r;
            int m   = m0 + row;
            int bb  = m >> 11;
            int nn  = m & 2047;
            int u   = k0 + (t & 15) * 4;     // 4-aligned -> stays in one head
            int hh  = u >> 5;
            int dd  = u & 31;
            float4 x4 = *(const float4*)
                &g_ctx[((((size_t)bb * kH + hh) * kN) + nn) * kD + dd];
            int kc = (t & 15) * 4;
            Xs[row][kc + 0] = x4.x; Xs[row][kc + 1] = x4.y;
            Xs[row][kc + 2] = x4.z; Xs[row][kc + 3] = x4.w;
            float4 w4 = *(const float4*)&Wo[(size_t)(k0 + row) * kU + c0 + kc];
            *(float4*)&Ws[row * 64 + kc] = w4;
        }
        __syncthreads();

        #pragma unroll 8
        for (int k = 0; k < 64; k++) {
            float a0 = Xs[4 * ty + 0][k];
            float a1 = Xs[4 * ty + 1][k];
            float a2 = Xs[4 * ty + 2][k];
            float a3 = Xs[4 * ty + 3][k];
            float4 b4 = *(const float4*)&Ws[k * 64 + 4 * tx];
            acc[0][0] += a0 * b4.x; acc[0][1] += a0 * b4.y; acc[0][2] += a0 * b4.z; acc[0][3] += a0 * b4.w;
            acc[1][0] += a1 * b4.x; acc[1][1] += a1 * b4.y; acc[1][2] += a1 * b4.z; acc[1][3] += a1 * b4.w;
            acc[2][0] += a2 * b4.x; acc[2][1] += a2 * b4.y; acc[2][2] += a2 * b4.z; acc[2][3] += a2 * b4.w;
            acc[3][0] += a3 * b4.x; acc[3][1] += a3 * b4.y; acc[3][2] += a3 * b4.z; acc[3][3] += a3 * b4.w;
        }
    }

    const float4 bias = *(const float4*)&bo[c0 + 4 * tx];
    #pragma unroll
    for (int i = 0; i < 4; i++) {
        int m = m0 + 4 * ty + i;
        *(float4*)&out[(size_t)m * kU + c0 + 4 * tx] =
            make_float4(acc[i][0] + bias.x, acc[i][1] + bias.y,
                        acc[i][2] + bias.z, acc[i][3] + bias.w);
    }
}

// ---------------------------------------------------------------------------
extern "C" void kernel_launch(void* const* d_in, const int* in_sizes, int n_in,
                              void* d_out, int out_size)
{
    const float* X   = (const float*)d_in[0];  // node_features [8,2048,256]
    const int*   adj = (const int*)d_in[1];    // adjacency   [8,2048,2048]
    const float* Wq  = (const float*)d_in[2];
    const float* Wk  = (const float*)d_in[3];
    const float* Wv  = (const float*)d_in[4];
    const float* Wo  = (const float*)d_in[5];
    const float* bo  = (const float*)d_in[6];
    float* out = (float*)d_out;

    proj_qkv_kernel<<<dim3(kM / 64, 12), 256>>>(X, Wq, Wk, Wv);
    attn_kernel<<<dim3(kB, kN / 32), 256>>>(adj);
    out_proj_kernel<<<dim3(kM / 64, 4), 256>>>(Wo, bo, out);
}

// round 4
// speedup vs baseline: 1.0006x; 1.0006x over previous
#include <cuda_runtime.h>
#include <math.h>

// Problem constants
static constexpr int kB = 8;
static constexpr int kN = 2048;
static constexpr int kU = 256;   // UNITS
static constexpr int kH = 8;     // heads
static constexpr int kD = 32;    // head dim
static constexpr int kM = kB * kN;  // 16384 rows

// Scratch (allocation-free rule: __device__ globals). 16 MB each.
__device__ __align__(256) float g_q[(size_t)kB * kH * kN * kD];
__device__ __align__(256) float g_k[(size_t)kB * kH * kN * kD];
__device__ __align__(256) float g_v[(size_t)kB * kH * kN * kD];
__device__ __align__(256) float g_ctx[(size_t)kB * kH * kN * kD];

// ---------------------------------------------------------------------------
// Kernel 1: fused QKV projection.
// OUT[m, c] = X[m, :] @ W[:, c] for W in {Wq, Wk, Wv} (c tiled over 768).
// Writes into g_q/g_k/g_v with [B, H, N, D] layout for the attention kernel.
// CTA: 64x64 output tile, 256 threads, 4x4 accum per thread.
// ---------------------------------------------------------------------------
__global__ __launch_bounds__(256) void proj_qkv_kernel(
    const float* __restrict__ X,
    const float* __restrict__ Wq,
    const float* __restrict__ Wk,
    const float* __restrict__ Wv)
{
    __shared__ float Xs[64][65];   // [row][k], +1 pad
    __shared__ float Ws[64 * 64];  // [k][col]

    const int t  = threadIdx.x;
    const int tx = t & 15;         // col group (4 cols)
    const int ty = t >> 4;         // row group (4 rows)
    const int m0  = blockIdx.x * 64;
    const int ci0 = blockIdx.y * 64;         // 0..767
    const int mat = ci0 >> 8;                // 0=Q,1=K,2=V
    const int c0  = ci0 & 255;               // col base within the matrix
    const float* __restrict__ W = (mat == 0) ? Wq : (mat == 1) ? Wk : Wv;

    float acc[4][4];
    #pragma unroll
    for (int i = 0; i < 4; i++)
        #pragma unroll
        for (int j = 0; j < 4; j++) acc[i][j] = 0.f;

    for (int k0 = 0; k0 < kU; k0 += 64) {
        __syncthreads();
        #pragma unroll
        for (int r = 0; r < 4; r++) {
            int row = (t >> 4) + 16 * r;     // 0..63
            int kc  = (t & 15) * 4;          // 0..60
            float4 x4 = *(const float4*)&X[(size_t)(m0 + row) * kU + k0 + kc];
            Xs[row][kc + 0] = x4.x; Xs[row][kc + 1] = x4.y;
            Xs[row][kc + 2] = x4.z; Xs[row][kc + 3] = x4.w;
            float4 w4 = *(const float4*)&W[(size_t)(k0 + row) * kU + c0 + kc];
            *(float4*)&Ws[row * 64 + kc] = w4;
        }
        __syncthreads();

        #pragma unroll 8
        for (int k = 0; k < 64; k++) {
            float a0 = Xs[4 * ty + 0][k];
            float a1 = Xs[4 * ty + 1][k];
            float a2 = Xs[4 * ty + 2][k];
            float a3 = Xs[4 * ty + 3][k];
            float4 b4 = *(const float4*)&Ws[k * 64 + 4 * tx];
            acc[0][0] += a0 * b4.x; acc[0][1] += a0 * b4.y; acc[0][2] += a0 * b4.z; acc[0][3] += a0 * b4.w;
            acc[1][0] += a1 * b4.x; acc[1][1] += a1 * b4.y; acc[1][2] += a1 * b4.z; acc[1][3] += a1 * b4.w;
            acc[2][0] += a2 * b4.x; acc[2][1] += a2 * b4.y; acc[2][2] += a2 * b4.z; acc[2][3] += a2 * b4.w;
            acc[3][0] += a3 * b4.x; acc[3][1] += a3 * b4.y; acc[3][2] += a3 * b4.z; acc[3][3] += a3 * b4.w;
        }
    }

    // Epilogue: scatter into [B, H, N, D] layout. 4 consecutive cols stay in one head.
    const int hh = (c0 + 4 * tx) >> 5;
    const int dd = (c0 + 4 * tx) & 31;
    float* __restrict__ dst = (mat == 0) ? g_q : (mat == 1) ? g_k : g_v;
    #pragma unroll
    for (int i = 0; i < 4; i++) {
        int m  = m0 + 4 * ty + i;
        int bb = m >> 11;       // /2048
        int nn = m & 2047;
        *(float4*)&dst[((((size_t)bb * kH + hh) * kN) + nn) * kD + dd] =
            make_float4(acc[i][0], acc[i][1], acc[i][2], acc[i][3]);
    }
}

// ---------------------------------------------------------------------------
// Kernel 2: masked multi-head attention, flash-style online softmax.
// CTA = (batch b, 32-query tile), 8 warps = 8 heads, lane = query.
// All heads share one adjacency tile (read once from DRAM).
// K/V streamed in 16-key tiles through smem; scores/ctx entirely in registers.
// ---------------------------------------------------------------------------
__global__ __launch_bounds__(256, 2) void attn_kernel(const int* __restrict__ adj)
{
    __shared__ float Ks[kH * 16 * kD];  // [h][kj][d]
    __shared__ float Vs[kH * 16 * kD];
    __shared__ int   adjs[16 * 33];     // [kj][qi], +1 pad -> conflict-free

    const int b    = blockIdx.x;
    const int q0   = blockIdx.y * 32;
    const int h    = threadIdx.x >> 5;   // warp = head
    const int lane = threadIdx.x & 31;   // lane = query within tile

    const float scale = 0.17677669529663687f;  // 1/sqrt(32)

    // Q row for this (b, h, q) in registers, pre-scaled.
    float q[32];
    {
        const float4* Qg =
            (const float4*)&g_q[((((size_t)b * kH + h) * kN) + q0 + lane) * kD];
        #pragma unroll
        for (int i = 0; i < 8; i++) {
            float4 v = Qg[i];
            q[4 * i + 0] = v.x * scale; q[4 * i + 1] = v.y * scale;
            q[4 * i + 2] = v.z * scale; q[4 * i + 3] = v.w * scale;
        }
    }

    float ctx[32];
    #pragma unroll
    for (int i = 0; i < 32; i++) ctx[i] = 0.f;
    float mrun = -1e30f;
    float lrun = 0.f;

    const float4* Kg = (const float4*)&g_k[(((size_t)b * kH + h) * kN) * kD];
    const float4* Vg = (const float4*)&g_v[(((size_t)b * kH + h) * kN) * kD];
    float4* Kd = (float4*)&Ks[h * 16 * kD];
    float4* Vd = (float4*)&Vs[h * 16 * kD];

    const int aqi = threadIdx.x >> 3;        // 0..31 query
    const int akj = (threadIdx.x & 7) * 2;   // 0..14 key (pairs)

    for (int kt = 0; kt < kN / 16; kt++) {
        const int k0 = kt * 16;
        __syncthreads();
        // Warp h loads its head's 16x32 K and V tiles (contiguous, coalesced).
        #pragma unroll
        for (int i = 0; i < 4; i++) {
            Kd[lane + 32 * i] = Kg[k0 * 8 + lane + 32 * i];
            Vd[lane + 32 * i] = Vg[k0 * 8 + lane + 32 * i];
        }
        // Adjacency tile [32 q][16 k], stored transposed [kj][qi].
        {
            int2 a2 = *(const int2*)&adj[(((size_t)b * kN) + q0 + aqi) * kN + k0 + akj];
            adjs[(akj + 0) * 33 + aqi] = a2.x;
            adjs[(akj + 1) * 33 + aqi] = a2.y;
        }
        __syncthreads();

        const float4* Kh = (const float4*)&Ks[h * 16 * kD];
        float p[16];
        float tmax = -1e30f;
        #pragma unroll
        for (int kj = 0; kj < 16; kj++) {
            float s0 = 0.f, s1 = 0.f, s2 = 0.f, s3 = 0.f;
            #pragma unroll
            for (int i = 0; i < 8; i++) {
                float4 kv = Kh[kj * 8 + i];  // warp-uniform -> smem broadcast
                s0 += q[4 * i + 0] * kv.x; s1 += q[4 * i + 1] * kv.y;
                s2 += q[4 * i + 2] * kv.z; s3 += q[4 * i + 3] * kv.w;
            }
            float s = (s0 + s1) + (s2 + s3);
            s = (adjs[kj * 33 + lane] > 0) ? s : -1e9f;  // same -1e9 as reference
            p[kj] = s;
            tmax = fmaxf(tmax, s);
        }

        const float mnew  = fmaxf(mrun, tmax);
        const float alpha = __expf(mrun - mnew);
        lrun *= alpha;
        #pragma unroll
        for (int i = 0; i < 32; i++) ctx[i] *= alpha;

        const float4* Vh = (const float4*)&Vs[h * 16 * kD];
        #pragma unroll
        for (int kj = 0; kj < 16; kj++) {
            float pv = __expf(p[kj] - mnew);
            lrun += pv;
            #pragma unroll
            for (int i = 0; i < 8; i++) {
                float4 vv = Vh[kj * 8 + i];
                ctx[4 * i + 0] += pv * vv.x; ctx[4 * i + 1] += pv * vv.y;
                ctx[4 * i + 2] += pv * vv.z; ctx[4 * i + 3] += pv * vv.w;
            }
        }
        mrun = mnew;
    }

    const float inv = 1.f / lrun;
    float4* Cg = (float4*)&g_ctx[((((size_t)b * kH + h) * kN) + q0 + lane) * kD];
    #pragma unroll
    for (int i = 0; i < 8; i++)
        Cg[i] = make_float4(ctx[4 * i + 0] * inv, ctx[4 * i + 1] * inv,
                            ctx[4 * i + 2] * inv, ctx[4 * i + 3] * inv);
}

// ---------------------------------------------------------------------------
// Kernel 3: output projection. OUT = CTX @ Wo + bo.
// CTX is read from the [B, H, N, D] layout (gathered per 32-wide head block).
// ---------------------------------------------------------------------------
__global__ __launch_bounds__(256) void out_proj_kernel(
    const float* __restrict__ Wo,
    const float* __restrict__ bo,
    float* __restrict__ out)
{
    __shared__ float Xs[64][65];
    __shared__ float Ws[64 * 64];

    const int t  = threadIdx.x;
    const int tx = t & 15;
    const int ty = t >> 4;
    const int m0 = blockIdx.x * 64;
    const int c0 = blockIdx.y * 64;

    float acc[4][4];
    #pragma unroll
    for (int i = 0; i < 4; i++)
        #pragma unroll
        for (int j = 0; j < 4; j++) acc[i][j] = 0.f;

    for (int k0 = 0; k0 < kU; k0 += 64) {
        __syncthreads();
        #pragma unroll
        for (int r = 0; r < 4; r++) {
            int row = (t >> 4) + 16 * r;
            int m   = m0 + row;
            int bb  = m >> 11;
            int nn  = m & 2047;
            int u   = k0 + (t & 15) * 4;     // 4-aligned -> stays in one head
            int hh  = u >> 5;
            int dd  = u & 31;
            float4 x4 = *(const float4*)
                &g_ctx[((((size_t)bb * kH + hh) * kN) + nn) * kD + dd];
            int kc = (t & 15) * 4;
            Xs[row][kc + 0] = x4.x; Xs[row][kc + 1] = x4.y;
            Xs[row][kc + 2] = x4.z; Xs[row][kc + 3] = x4.w;
            float4 w4 = *(const float4*)&Wo[(size_t)(k0 + row) * kU + c0 + kc];
            *(float4*)&Ws[row * 64 + kc] = w4;
        }
        __syncthreads();

        #pragma unroll 8
        for (int k = 0; k < 64; k++) {
            float a0 = Xs[4 * ty + 0][k];
            float a1 = Xs[4 * ty + 1][k];
            float a2 = Xs[4 * ty + 2][k];
            float a3 = Xs[4 * ty + 3][k];
            float4 b4 = *(const float4*)&Ws[k * 64 + 4 * tx];
            acc[0][0] += a0 * b4.x; acc[0][1] += a0 * b4.y; acc[0][2] += a0 * b4.z; acc[0][3] += a0 * b4.w;
            acc[1][0] += a1 * b4.x; acc[1][1] += a1 * b4.y; acc[1][2] += a1 * b4.z; acc[1][3] += a1 * b4.w;
            acc[2][0] += a2 * b4.x; acc[2][1] += a2 * b4.y; acc[2][2] += a2 * b4.z; acc[2][3] += a2 * b4.w;
            acc[3][0] += a3 * b4.x; acc[3][1] += a3 * b4.y; acc[3][2] += a3 * b4.z; acc[3][3] += a3 * b4.w;
        }
    }

    const float4 bias = *(const float4*)&bo[c0 + 4 * tx];
    #pragma unroll
    for (int i = 0; i < 4; i++) {
        int m = m0 + 4 * ty + i;
        *(float4*)&out[(size_t)m * kU + c0 + 4 * tx] =
            make_float4(acc[i][0] + bias.x, acc[i][1] + bias.y,
                        acc[i][2] + bias.z, acc[i][3] + bias.w);
    }
}

// ---------------------------------------------------------------------------
extern "C" void kernel_launch(void* const* d_in, const int* in_sizes, int n_in,
                              void* d_out, int out_size)
{
    const float* X   = (const float*)d_in[0];  // node_features [8,2048,256]
    const int*   adj = (const int*)d_in[1];    // adjacency   [8,2048,2048]
    const float* Wq  = (const float*)d_in[2];
    const float* Wk  = (const float*)d_in[3];
    const float* Wv  = (const float*)d_in[4];
    const float* Wo  = (const float*)d_in[5];
    const float* bo  = (const float*)d_in[6];
    float* out = (float*)d_out;

    proj_qkv_kernel<<<dim3(kM / 64, 12), 256>>>(X, Wq, Wk, Wv);
    attn_kernel<<<dim3(kB, kN / 32), 256>>>(adj);
    out_proj_kernel<<<dim3(kM / 64, 4), 256>>>(Wo, bo, out);
}

// round 5
// speedup vs baseline: 1.0008x; 1.0002x over previous
#include <cuda_runtime.h>
#include <math.h>

// Problem constants
static constexpr int kB = 8;
static constexpr int kN = 2048;
static constexpr int kU = 256;   // UNITS
static constexpr int kH = 8;     // heads
static constexpr int kD = 32;    // head dim
static constexpr int kM = kB * kN;  // 16384 rows

// Scratch (allocation-free rule: __device__ globals). 16 MB each.
__device__ __align__(256) float g_q[(size_t)kB * kH * kN * kD];
__device__ __align__(256) float g_k[(size_t)kB * kH * kN * kD];
__device__ __align__(256) float g_v[(size_t)kB * kH * kN * kD];
__device__ __align__(256) float g_ctx[(size_t)kB * kH * kN * kD];

// ---------------------------------------------------------------------------
// Kernel 1: fused QKV projection.
// OUT[m, c] = X[m, :] @ W[:, c] for W in {Wq, Wk, Wv} (c tiled over 768).
// Writes into g_q/g_k/g_v with [B, H, N, D] layout for the attention kernel.
// CTA: 64x64 output tile, 256 threads, 4x4 accum per thread.
// ---------------------------------------------------------------------------
__global__ __launch_bounds__(256) void proj_qkv_kernel(
    const float* __restrict__ X,
    const float* __restrict__ Wq,
    const float* __restrict__ Wk,
    const float* __restrict__ Wv)
{
    __shared__ float Xs[64][65];   // [row][k], +1 pad
    __shared__ float Ws[64 * 64];  // [k][col]

    const int t  = threadIdx.x;
    const int tx = t & 15;         // col group (4 cols)
    const int ty = t >> 4;         // row group (4 rows)
    const int m0  = blockIdx.x * 64;
    const int ci0 = blockIdx.y * 64;         // 0..767
    const int mat = ci0 >> 8;                // 0=Q,1=K,2=V
    const int c0  = ci0 & 255;               // col base within the matrix
    const float* __restrict__ W = (mat == 0) ? Wq : (mat == 1) ? Wk : Wv;

    float acc[4][4];
    #pragma unroll
    for (int i = 0; i < 4; i++)
        #pragma unroll
        for (int j = 0; j < 4; j++) acc[i][j] = 0.f;

    for (int k0 = 0; k0 < kU; k0 += 64) {
        __syncthreads();
        #pragma unroll
        for (int r = 0; r < 4; r++) {
            int row = (t >> 4) + 16 * r;     // 0..63
            int kc  = (t & 15) * 4;          // 0..60
            float4 x4 = *(const float4*)&X[(size_t)(m0 + row) * kU + k0 + kc];
            Xs[row][kc + 0] = x4.x; Xs[row][kc + 1] = x4.y;
            Xs[row][kc + 2] = x4.z; Xs[row][kc + 3] = x4.w;
            float4 w4 = *(const float4*)&W[(size_t)(k0 + row) * kU + c0 + kc];
            *(float4*)&Ws[row * 64 + kc] = w4;
        }
        __syncthreads();

        #pragma unroll 8
        for (int k = 0; k < 64; k++) {
            float a0 = Xs[4 * ty + 0][k];
            float a1 = Xs[4 * ty + 1][k];
            float a2 = Xs[4 * ty + 2][k];
            float a3 = Xs[4 * ty + 3][k];
            float4 b4 = *(const float4*)&Ws[k * 64 + 4 * tx];
            acc[0][0] += a0 * b4.x; acc[0][1] += a0 * b4.y; acc[0][2] += a0 * b4.z; acc[0][3] += a0 * b4.w;
            acc[1][0] += a1 * b4.x; acc[1][1] += a1 * b4.y; acc[1][2] += a1 * b4.z; acc[1][3] += a1 * b4.w;
            acc[2][0] += a2 * b4.x; acc[2][1] += a2 * b4.y; acc[2][2] += a2 * b4.z; acc[2][3] += a2 * b4.w;
            acc[3][0] += a3 * b4.x; acc[3][1] += a3 * b4.y; acc[3][2] += a3 * b4.z; acc[3][3] += a3 * b4.w;
        }
    }

    // Epilogue: scatter into [B, H, N, D] layout. 4 consecutive cols stay in one head.
    const int hh = (c0 + 4 * tx) >> 5;
    const int dd = (c0 + 4 * tx) & 31;
    float* __restrict__ dst = (mat == 0) ? g_q : (mat == 1) ? g_k : g_v;
    #pragma unroll
    for (int i = 0; i < 4; i++) {
        int m  = m0 + 4 * ty + i;
        int bb = m >> 11;       // /2048
        int nn = m & 2047;
        *(float4*)&dst[((((size_t)bb * kH + hh) * kN) + nn) * kD + dd] =
            make_float4(acc[i][0], acc[i][1], acc[i][2], acc[i][3]);
    }
}

// ---------------------------------------------------------------------------
// Kernel 2: masked multi-head attention, flash-style online softmax.
// CTA = (batch b, 32-query tile), 8 warps = 8 heads, lane = query.
// All heads share one adjacency tile (read once from DRAM).
// K/V streamed in 16-key tiles through smem; scores/ctx entirely in registers.
// ---------------------------------------------------------------------------
__global__ __launch_bounds__(256, 2) void attn_kernel(const int* __restrict__ adj)
{
    __shared__ float Ks[kH * 16 * kD];  // [h][kj][d]
    __shared__ float Vs[kH * 16 * kD];
    __shared__ int   adjs[16 * 33];     // [kj][qi], +1 pad -> conflict-free

    const int b    = blockIdx.x;
    const int q0   = blockIdx.y * 32;
    const int h    = threadIdx.x >> 5;   // warp = head
    const int lane = threadIdx.x & 31;   // lane = query within tile

    const float scale = 0.17677669529663687f;  // 1/sqrt(32)

    // Q row for this (b, h, q) in registers, pre-scaled.
    float q[32];
    {
        const float4* Qg =
            (const float4*)&g_q[((((size_t)b * kH + h) * kN) + q0 + lane) * kD];
        #pragma unroll
        for (int i = 0; i < 8; i++) {
            float4 v = Qg[i];
            q[4 * i + 0] = v.x * scale; q[4 * i + 1] = v.y * scale;
            q[4 * i + 2] = v.z * scale; q[4 * i + 3] = v.w * scale;
        }
    }

    float ctx[32];
    #pragma unroll
    for (int i = 0; i < 32; i++) ctx[i] = 0.f;
    float mrun = -1e30f;
    float lrun = 0.f;

    const float4* Kg = (const float4*)&g_k[(((size_t)b * kH + h) * kN) * kD];
    const float4* Vg = (const float4*)&g_v[(((size_t)b * kH + h) * kN) * kD];
    float4* Kd = (float4*)&Ks[h * 16 * kD];
    float4* Vd = (float4*)&Vs[h * 16 * kD];

    const int aqi = threadIdx.x >> 3;        // 0..31 query
    const int akj = (threadIdx.x & 7) * 2;   // 0..14 key (pairs)

    for (int kt = 0; kt < kN / 16; kt++) {
        const int k0 = kt * 16;
        __syncthreads();
        // Warp h loads its head's 16x32 K and V tiles (contiguous, coalesced).
        #pragma unroll
        for (int i = 0; i < 4; i++) {
            Kd[lane + 32 * i] = Kg[k0 * 8 + lane + 32 * i];
            Vd[lane + 32 * i] = Vg[k0 * 8 + lane + 32 * i];
        }
        // Adjacency tile [32 q][16 k], stored transposed [kj][qi].
        {
            int2 a2 = *(const int2*)&adj[(((size_t)b * kN) + q0 + aqi) * kN + k0 + akj];
            adjs[(akj + 0) * 33 + aqi] = a2.x;
            adjs[(akj + 1) * 33 + aqi] = a2.y;
        }
        __syncthreads();

        const float4* Kh = (const float4*)&Ks[h * 16 * kD];
        float p[16];
        float tmax = -1e30f;
        #pragma unroll
        for (int kj = 0; kj < 16; kj++) {
            float s0 = 0.f, s1 = 0.f, s2 = 0.f, s3 = 0.f;
            #pragma unroll
            for (int i = 0; i < 8; i++) {
                float4 kv = Kh[kj * 8 + i];  // warp-uniform -> smem broadcast
                s0 += q[4 * i + 0] * kv.x; s1 += q[4 * i + 1] * kv.y;
                s2 += q[4 * i + 2] * kv.z; s3 += q[4 * i + 3] * kv.w;
            }
            float s = (s0 + s1) + (s2 + s3);
            s = (adjs[kj * 33 + lane] > 0) ? s : -1e9f;  // same -1e9 as reference
            p[kj] = s;
            tmax = fmaxf(tmax, s);
        }

        const float mnew  = fmaxf(mrun, tmax);
        const float alpha = __expf(mrun - mnew);
        lrun *= alpha;
        #pragma unroll
        for (int i = 0; i < 32; i++) ctx[i] *= alpha;

        const float4* Vh = (const float4*)&Vs[h * 16 * kD];
        #pragma unroll
        for (int kj = 0; kj < 16; kj++) {
            float pv = __expf(p[kj] - mnew);
            lrun += pv;
            #pragma unroll
            for (int i = 0; i < 8; i++) {
                float4 vv = Vh[kj * 8 + i];
                ctx[4 * i + 0] += pv * vv.x; ctx[4 * i + 1] += pv * vv.y;
                ctx[4 * i + 2] += pv * vv.z; ctx[4 * i + 3] += pv * vv.w;
            }
        }
        mrun = mnew;
    }

    const float inv = 1.f / lrun;
    float4* Cg = (float4*)&g_ctx[((((size_t)b * kH + h) * kN) + q0 + lane) * kD];
    #pragma unroll
    for (int i = 0; i < 8; i++)
        Cg[i] = make_float4(ctx[4 * i + 0] * inv, ctx[4 * i + 1] * inv,
                            ctx[4 * i + 2] * inv, ctx[4 * i + 3] * inv);
}

// ---------------------------------------------------------------------------
// Kernel 3: output projection. OUT = CTX @ Wo + bo.
// CTX is read from the [B, H, N, D] layout (gathered per 32-wide head block).
// ---------------------------------------------------------------------------
__global__ __launch_bounds__(256) void out_proj_kernel(
    const float* __restrict__ Wo,
    const float* __restrict__ bo,
    float* __restrict__ out)
{
    __shared__ float Xs[64][65];
    __shared__ float Ws[64 * 64];

    const int t  = threadIdx.x;
    const int tx = t & 15;
    const int ty = t >> 4;
    const int m0 = blockIdx.x * 64;
    const int c0 = blockIdx.y * 64;

    float acc[4][4];
    #pragma unroll
    for (int i = 0; i < 4; i++)
        #pragma unroll
        for (int j = 0; j < 4; j++) acc[i][j] = 0.f;

    for (int k0 = 0; k0 < kU; k0 += 64) {
        __syncthreads();
        #pragma unroll
        for (int r = 0; r < 4; r++) {
            int row = (t >> 4) + 16 * r;
            int m   = m0 + row;
            int bb  = m >> 11;
            int nn  = m & 2047;
            int u   = k0 + (t & 15) * 4;     // 4-aligned -> stays in one head
            int hh  = u >> 5;
            int dd  = u & 31;
            float4 x4 = *(const float4*)
                &g_ctx[((((size_t)bb * kH + hh) * kN) + nn) * kD + dd];
            int kc = (t & 15) * 4;
            Xs[row][kc + 0] = x4.x; Xs[row][kc + 1] = x4.y;
            Xs[row][kc + 2] = x4.z; Xs[row][kc + 3] = x4.w;
            float4 w4 = *(const float4*)&Wo[(size_t)(k0 + row) * kU + c0 + kc];
            *(float4*)&Ws[row * 64 + kc] = w4;
        }
        __syncthreads();

        #pragma unroll 8
        for (int k = 0; k < 64; k++) {
            float a0 = Xs[4 * ty + 0][k];
            float a1 = Xs[4 * ty + 1][k];
            float a2 = Xs[4 * ty + 2][k];
            float a3 = Xs[4 * ty + 3][k];
            float4 b4 = *(const float4*)&Ws[k * 64 + 4 * tx];
            acc[0][0] += a0 * b4.x; acc[0][1] += a0 * b4.y; acc[0][2] += a0 * b4.z; acc[0][3] += a0 * b4.w;
            acc[1][0] += a1 * b4.x; acc[1][1] += a1 * b4.y; acc[1][2] += a1 * b4.z; acc[1][3] += a1 * b4.w;
            acc[2][0] += a2 * b4.x; acc[2][1] += a2 * b4.y; acc[2][2] += a2 * b4.z; acc[2][3] += a2 * b4.w;
            acc[3][0] += a3 * b4.x; acc[3][1] += a3 * b4.y; acc[3][2] += a3 * b4.z; acc[3][3] += a3 * b4.w;
        }
    }

    const float4 bias = *(const float4*)&bo[c0 + 4 * tx];
    #pragma unroll
    for (int i = 0; i < 4; i++) {
        int m = m0 + 4 * ty + i;
        *(float4*)&out[(size_t)m * kU + c0 + 4 * tx] =
            make_float4(acc[i][0] + bias.x, acc[i][1] + bias.y,
                        acc[i][2] + bias.z, acc[i][3] + bias.w);
    }
}

// ---------------------------------------------------------------------------
extern "C" void kernel_launch(void* const* d_in, const int* in_sizes, int n_in,
                              void* d_out, int out_size)
{
    const float* X   = (const float*)d_in[0];  // node_features [8,2048,256]
    const int*   adj = (const int*)d_in[1];    // adjacency   [8,2048,2048]
    const float* Wq  = (const float*)d_in[2];
    const float* Wk  = (const float*)d_in[3];
    const float* Wv  = (const float*)d_in[4];
    const float* Wo  = (const float*)d_in[5];
    const float* bo  = (const float*)d_in[6];
    float* out = (float*)d_out;

    proj_qkv_kernel<<<dim3(kM / 64, 12), 256>>>(X, Wq, Wk, Wv);
    attn_kernel<<<dim3(kB, kN / 32), 256>>>(adj);
    out_proj_kernel<<<dim3(kM / 64, 4), 256>>>(Wo, bo, out);
}

// round 6
// speedup vs baseline: 1.0016x; 1.0008x over previous
#include <cuda_runtime.h>
#include <math.h>

// Problem constants
static constexpr int kB = 8;
static constexpr int kN = 2048;
static constexpr int kU = 256;   // UNITS
static constexpr int kH = 8;     // heads
static constexpr int kD = 32;    // head dim
static constexpr int kM = kB * kN;  // 16384 rows

// Scratch (allocation-free rule: __device__ globals). 16 MB each.
__device__ __align__(256) float g_q[(size_t)kB * kH * kN * kD];
__device__ __align__(256) float g_k[(size_t)kB * kH * kN * kD];
__device__ __align__(256) float g_v[(size_t)kB * kH * kN * kD];
__device__ __align__(256) float g_ctx[(size_t)kB * kH * kN * kD];

// ---------------------------------------------------------------------------
// Kernel 1: fused QKV projection.
// OUT[m, c] = X[m, :] @ W[:, c] for W in {Wq, Wk, Wv} (c tiled over 768).
// Writes into g_q/g_k/g_v with [B, H, N, D] layout for the attention kernel.
// CTA: 64x64 output tile, 256 threads, 4x4 accum per thread.
// ---------------------------------------------------------------------------
__global__ __launch_bounds__(256) void proj_qkv_kernel(
    const float* __restrict__ X,
    const float* __restrict__ Wq,
    const float* __restrict__ Wk,
    const float* __restrict__ Wv)
{
    __shared__ float Xs[64][65];   // [row][k], +1 pad
    __shared__ float Ws[64 * 64];  // [k][col]

    const int t  = threadIdx.x;
    const int tx = t & 15;         // col group (4 cols)
    const int ty = t >> 4;         // row group (4 rows)
    const int m0  = blockIdx.x * 64;
    const int ci0 = blockIdx.y * 64;         // 0..767
    const int mat = ci0 >> 8;                // 0=Q,1=K,2=V
    const int c0  = ci0 & 255;               // col base within the matrix
    const float* __restrict__ W = (mat == 0) ? Wq : (mat == 1) ? Wk : Wv;

    float acc[4][4];
    #pragma unroll
    for (int i = 0; i < 4; i++)
        #pragma unroll
        for (int j = 0; j < 4; j++) acc[i][j] = 0.f;

    for (int k0 = 0; k0 < kU; k0 += 64) {
        __syncthreads();
        #pragma unroll
        for (int r = 0; r < 4; r++) {
            int row = (t >> 4) + 16 * r;     // 0..63
            int kc  = (t & 15) * 4;          // 0..60
            float4 x4 = *(const float4*)&X[(size_t)(m0 + row) * kU + k0 + kc];
            Xs[row][kc + 0] = x4.x; Xs[row][kc + 1] = x4.y;
            Xs[row][kc + 2] = x4.z; Xs[row][kc + 3] = x4.w;
            float4 w4 = *(const float4*)&W[(size_t)(k0 + row) * kU + c0 + kc];
            *(float4*)&Ws[row * 64 + kc] = w4;
        }
        __syncthreads();

        #pragma unroll 8
        for (int k = 0; k < 64; k++) {
            float a0 = Xs[4 * ty + 0][k];
            float a1 = Xs[4 * ty + 1][k];
            float a2 = Xs[4 * ty + 2][k];
            float a3 = Xs[4 * ty + 3][k];
            float4 b4 = *(const float4*)&Ws[k * 64 + 4 * tx];
            acc[0][0] += a0 * b4.x; acc[0][1] += a0 * b4.y; acc[0][2] += a0 * b4.z; acc[0][3] += a0 * b4.w;
            acc[1][0] += a1 * b4.x; acc[1][1] += a1 * b4.y; acc[1][2] += a1 * b4.z; acc[1][3] += a1 * b4.w;
            acc[2][0] += a2 * b4.x; acc[2][1] += a2 * b4.y; acc[2][2] += a2 * b4.z; acc[2][3] += a2 * b4.w;
            acc[3][0] += a3 * b4.x; acc[3][1] += a3 * b4.y; acc[3][2] += a3 * b4.z; acc[3][3] += a3 * b4.w;
        }
    }

    // Epilogue: scatter into [B, H, N, D] layout. 4 consecutive cols stay in one head.
    const int hh = (c0 + 4 * tx) >> 5;
    const int dd = (c0 + 4 * tx) & 31;
    float* __restrict__ dst = (mat == 0) ? g_q : (mat == 1) ? g_k : g_v;
    #pragma unroll
    for (int i = 0; i < 4; i++) {
        int m  = m0 + 4 * ty + i;
        int bb = m >> 11;       // /2048
        int nn = m & 2047;
        *(float4*)&dst[((((size_t)bb * kH + hh) * kN) + nn) * kD + dd] =
            make_float4(acc[i][0], acc[i][1], acc[i][2], acc[i][3]);
    }
}

// ---------------------------------------------------------------------------
// Kernel 2: masked multi-head attention, flash-style online softmax.
// CTA = (batch b, 32-query tile), 8 warps = 8 heads, lane = query.
// All heads share one adjacency tile (read once from DRAM).
// K/V streamed in 16-key tiles through smem; scores/ctx entirely in registers.
// ---------------------------------------------------------------------------
__global__ __launch_bounds__(256, 2) void attn_kernel(const int* __restrict__ adj)
{
    __shared__ float Ks[kH * 16 * kD];  // [h][kj][d]
    __shared__ float Vs[kH * 16 * kD];
    __shared__ int   adjs[16 * 33];     // [kj][qi], +1 pad -> conflict-free

    const int b    = blockIdx.x;
    const int q0   = blockIdx.y * 32;
    const int h    = threadIdx.x >> 5;   // warp = head
    const int lane = threadIdx.x & 31;   // lane = query within tile

    const float scale = 0.17677669529663687f;  // 1/sqrt(32)

    // Q row for this (b, h, q) in registers, pre-scaled.
    float q[32];
    {
        const float4* Qg =
            (const float4*)&g_q[((((size_t)b * kH + h) * kN) + q0 + lane) * kD];
        #pragma unroll
        for (int i = 0; i < 8; i++) {
            float4 v = Qg[i];
            q[4 * i + 0] = v.x * scale; q[4 * i + 1] = v.y * scale;
            q[4 * i + 2] = v.z * scale; q[4 * i + 3] = v.w * scale;
        }
    }

    float ctx[32];
    #pragma unroll
    for (int i = 0; i < 32; i++) ctx[i] = 0.f;
    float mrun = -1e30f;
    float lrun = 0.f;

    const float4* Kg = (const float4*)&g_k[(((size_t)b * kH + h) * kN) * kD];
    const float4* Vg = (const float4*)&g_v[(((size_t)b * kH + h) * kN) * kD];
    float4* Kd = (float4*)&Ks[h * 16 * kD];
    float4* Vd = (float4*)&Vs[h * 16 * kD];

    const int aqi = threadIdx.x >> 3;        // 0..31 query
    const int akj = (threadIdx.x & 7) * 2;   // 0..14 key (pairs)

    for (int kt = 0; kt < kN / 16; kt++) {
        const int k0 = kt * 16;
        __syncthreads();
        // Warp h loads its head's 16x32 K and V tiles (contiguous, coalesced).
        #pragma unroll
        for (int i = 0; i < 4; i++) {
            Kd[lane + 32 * i] = Kg[k0 * 8 + lane + 32 * i];
            Vd[lane + 32 * i] = Vg[k0 * 8 + lane + 32 * i];
        }
        // Adjacency tile [32 q][16 k], stored transposed [kj][qi].
        {
            int2 a2 = *(const int2*)&adj[(((size_t)b * kN) + q0 + aqi) * kN + k0 + akj];
            adjs[(akj + 0) * 33 + aqi] = a2.x;
            adjs[(akj + 1) * 33 + aqi] = a2.y;
        }
        __syncthreads();

        const float4* Kh = (const float4*)&Ks[h * 16 * kD];
        float p[16];
        float tmax = -1e30f;
        #pragma unroll
        for (int kj = 0; kj < 16; kj++) {
            float s0 = 0.f, s1 = 0.f, s2 = 0.f, s3 = 0.f;
            #pragma unroll
            for (int i = 0; i < 8; i++) {
                float4 kv = Kh[kj * 8 + i];  // warp-uniform -> smem broadcast
                s0 += q[4 * i + 0] * kv.x; s1 += q[4 * i + 1] * kv.y;
                s2 += q[4 * i + 2] * kv.z; s3 += q[4 * i + 3] * kv.w;
            }
            float s = (s0 + s1) + (s2 + s3);
            s = (adjs[kj * 33 + lane] > 0) ? s : -1e9f;  // same -1e9 as reference
            p[kj] = s;
            tmax = fmaxf(tmax, s);
        }

        const float mnew  = fmaxf(mrun, tmax);
        const float alpha = __expf(mrun - mnew);
        lrun *= alpha;
        #pragma unroll
        for (int i = 0; i < 32; i++) ctx[i] *= alpha;

        const float4* Vh = (const float4*)&Vs[h * 16 * kD];
        #pragma unroll
        for (int kj = 0; kj < 16; kj++) {
            float pv = __expf(p[kj] - mnew);
            lrun += pv;
            #pragma unroll
            for (int i = 0; i < 8; i++) {
                float4 vv = Vh[kj * 8 + i];
                ctx[4 * i + 0] += pv * vv.x; ctx[4 * i + 1] += pv * vv.y;
                ctx[4 * i + 2] += pv * vv.z; ctx[4 * i + 3] += pv * vv.w;
            }
        }
        mrun = mnew;
    }

    const float inv = 1.f / lrun;
    float4* Cg = (float4*)&g_ctx[((((size_t)b * kH + h) * kN) + q0 + lane) * kD];
    #pragma unroll
    for (int i = 0; i < 8; i++)
        Cg[i] = make_float4(ctx[4 * i + 0] * inv, ctx[4 * i + 1] * inv,
                            ctx[4 * i + 2] * inv, ctx[4 * i + 3] * inv);
}

// ---------------------------------------------------------------------------
// Kernel 3: output projection. OUT = CTX @ Wo + bo.
// CTX is read from the [B, H, N, D] layout (gathered per 32-wide head block).
// ---------------------------------------------------------------------------
__global__ __launch_bounds__(256) void out_proj_kernel(
    const float* __restrict__ Wo,
    const float* __restrict__ bo,
    float* __restrict__ out)
{
    __shared__ float Xs[64][65];
    __shared__ float Ws[64 * 64];

    const int t  = threadIdx.x;
    const int tx = t & 15;
    const int ty = t >> 4;
    const int m0 = blockIdx.x * 64;
    const int c0 = blockIdx.y * 64;

    float acc[4][4];
    #pragma unroll
    for (int i = 0; i < 4; i++)
        #pragma unroll
        for (int j = 0; j < 4; j++) acc[i][j] = 0.f;

    for (int k0 = 0; k0 < kU; k0 += 64) {
        __syncthreads();
        #pragma unroll
        for (int r = 0; r < 4; r++) {
            int row = (t >> 4) + 16 * r;
            int m   = m0 + row;
            int bb  = m >> 11;
            int nn  = m & 2047;
            int u   = k0 + (t & 15) * 4;     // 4-aligned -> stays in one head
            int hh  = u >> 5;
            int dd  = u & 31;
            float4 x4 = *(const float4*)
                &g_ctx[((((size_t)bb * kH + hh) * kN) + nn) * kD + dd];
            int kc = (t & 15) * 4;
            Xs[row][kc + 0] = x4.x; Xs[row][kc + 1] = x4.y;
            Xs[row][kc + 2] = x4.z; Xs[row][kc + 3] = x4.w;
            float4 w4 = *(const float4*)&Wo[(size_t)(k0 + row) * kU + c0 + kc];
            *(float4*)&Ws[row * 64 + kc] = w4;
        }
        __syncthreads();

        #pragma unroll 8
        for (int k = 0; k < 64; k++) {
            float a0 = Xs[4 * ty + 0][k];
            float a1 = Xs[4 * ty + 1][k];
            float a2 = Xs[4 * ty + 2][k];
            float a3 = Xs[4 * ty + 3][k];
            float4 b4 = *(const float4*)&Ws[k * 64 + 4 * tx];
            acc[0][0] += a0 * b4.x; acc[0][1] += a0 * b4.y; acc[0][2] += a0 * b4.z; acc[0][3] += a0 * b4.w;
            acc[1][0] += a1 * b4.x; acc[1][1] += a1 * b4.y; acc[1][2] += a1 * b4.z; acc[1][3] += a1 * b4.w;
            acc[2][0] += a2 * b4.x; acc[2][1] += a2 * b4.y; acc[2][2] += a2 * b4.z; acc[2][3] += a2 * b4.w;
            acc[3][0] += a3 * b4.x; acc[3][1] += a3 * b4.y; acc[3][2] += a3 * b4.z; acc[3][3] += a3 * b4.w;
        }
    }

    const float4 bias = *(const float4*)&bo[c0 + 4 * tx];
    #pragma unroll
    for (int i = 0; i < 4; i++) {
        int m = m0 + 4 * ty + i;
        *(float4*)&out[(size_t)m * kU + c0 + 4 * tx] =
            make_float4(acc[i][0] + bias.x, acc[i][1] + bias.y,
                        acc[i][2] + bias.z, acc[i][3] + bias.w);
    }
}

// ---------------------------------------------------------------------------
extern "C" void kernel_launch(void* const* d_in, const int* in_sizes, int n_in,
                              void* d_out, int out_size)
{
    const float* X   = (const float*)d_in[0];  // node_features [8,2048,256]
    const int*   adj = (const int*)d_in[1];    // adjacency   [8,2048,2048]
    const float* Wq  = (const float*)d_in[2];
    const float* Wk  = (const float*)d_in[3];
    const float* Wv  = (const float*)d_in[4];
    const float* Wo  = (const float*)d_in[5];
    const float* bo  = (const float*)d_in[6];
    float* out = (float*)d_out;

    proj_qkv_kernel<<<dim3(kM / 64, 12), 256>>>(X, Wq, Wk, Wv);
    attn_kernel<<<dim3(kB, kN / 32), 256>>>(adj);
    out_proj_kernel<<<dim3(kM / 64, 4), 256>>>(Wo, bo, out);
}